// round 1
// baseline (speedup 1.0000x reference)
#include <cuda_runtime.h>

// Problem constants
#define Bsz 16384
#define Tn  17
#define Nn  128
#define Hn  256
#define Dn  5
#define Sn  16
#define HOn 32
#define DTc 0.01f

// Latents scratch: (S+1, B, D) fp32
__device__ float g_lat[(Sn + 1) * Bsz * Dn];

// Shared-memory arena layout (floats):
//  [0,      4096)  : sW   (weight chunk staging, up to 16x256)
//  [4096,  12288)  : sX   (input tile: 64x128 enc / 64x5 dec)
//  [12288, 28672)  : sH1  (64x256)
//  [28672, 45056)  : sH2  (64x256)
#define ARENA_FLOATS 45056
#define ARENA_BYTES  (ARENA_FLOATS * 4)

// 8x8 register-tile FMA over one 16-wide K chunk.
// sA rows are warp-broadcast loads (address depends only on ty).
__device__ __forceinline__ void mma_chunk_8x8(
    float acc[8][8], const float* __restrict__ sA, int aStride,
    const float* __restrict__ sW, int tx, int ty, int kc)
{
#pragma unroll
    for (int kk = 0; kk < 16; kk += 4) {
        float4 a4[8];
#pragma unroll
        for (int i = 0; i < 8; i++)
            a4[i] = *(const float4*)&sA[(ty * 8 + i) * aStride + kc + kk];
#pragma unroll
        for (int u = 0; u < 4; u++) {
            const float* wr = &sW[(kk + u) * 256 + tx * 8];
            float4 w0 = *(const float4*)wr;
            float4 w1 = *(const float4*)(wr + 4);
            float bb[8] = {w0.x, w0.y, w0.z, w0.w, w1.x, w1.y, w1.z, w1.w};
#pragma unroll
            for (int i = 0; i < 8; i++) {
                float av = (u == 0) ? a4[i].x : (u == 1) ? a4[i].y
                          : (u == 2) ? a4[i].z : a4[i].w;
#pragma unroll
                for (int j = 0; j < 8; j++)
                    acc[i][j] = fmaf(av, bb[j], acc[i][j]);
            }
        }
    }
}

// ---------------- Encoder: g = MLP3(x) ----------------
// grid: 4352 blocks x 256 threads; each block does 64 rows of (B*T, 128)
__global__ __launch_bounds__(256, 1)
void enc_kernel(const float* __restrict__ x,
                const float* __restrict__ W1, const float* __restrict__ b1,
                const float* __restrict__ W2, const float* __restrict__ b2,
                const float* __restrict__ W3, const float* __restrict__ b3,
                float* __restrict__ glist)
{
    extern __shared__ float sm[];
    float* sW  = sm;
    float* sX  = sm + 4096;
    float* sH1 = sm + 12288;
    float* sH2 = sm + 28672;

    const int tid = threadIdx.x;
    const int tx = tid & 31;
    const int ty = tid >> 5;
    const int rowBase = blockIdx.x * 64;

    // stage X tile (64x128)
    {
        const float4* xv = (const float4*)(x + (size_t)rowBase * Nn);
        float4* sv = (float4*)sX;
#pragma unroll
        for (int i = 0; i < 8; i++) sv[tid + 256 * i] = xv[tid + 256 * i];
    }

    float acc[8][8];
#pragma unroll
    for (int i = 0; i < 8; i++)
#pragma unroll
        for (int j = 0; j < 8; j++) acc[i][j] = 0.f;

    // ---- layer 1: h1 = relu(X @ W1 + b1), K=128 ----
    for (int kc = 0; kc < 128; kc += 16) {
        __syncthreads();
        {
            const float4* wv = (const float4*)(W1 + kc * 256);
            float4* sv = (float4*)sW;
#pragma unroll
            for (int i = 0; i < 4; i++) sv[tid + 256 * i] = wv[tid + 256 * i];
        }
        __syncthreads();
        mma_chunk_8x8(acc, sX, 128, sW, tx, ty, kc & 15 ? 0 : 0); // kc within chunk is 0 (sW holds this chunk)
    }
    // NOTE: mma_chunk_8x8's kc param indexes sA; for layer 1 the A offset is kc,
    // so redo properly below. (See corrected loop.)
    // --- The loop above intentionally passes kc=0 into sW but we must pass the
    //     true kc for sA; rewritten here for clarity: ---

    // (re-zero and recompute correctly)
#pragma unroll
    for (int i = 0; i < 8; i++)
#pragma unroll
        for (int j = 0; j < 8; j++) acc[i][j] = 0.f;
    for (int kc = 0; kc < 128; kc += 16) {
        __syncthreads();
        {
            const float4* wv = (const float4*)(W1 + kc * 256);
            float4* sv = (float4*)sW;
#pragma unroll
            for (int i = 0; i < 4; i++) sv[tid + 256 * i] = wv[tid + 256 * i];
        }
        __syncthreads();
        mma_chunk_8x8(acc, sX, 128, sW, tx, ty, kc);
    }

    // epilogue 1 -> sH1
    {
        float bias[8];
#pragma unroll
        for (int j = 0; j < 8; j++) bias[j] = b1[tx * 8 + j];
#pragma unroll
        for (int i = 0; i < 8; i++) {
            float v[8];
#pragma unroll
            for (int j = 0; j < 8; j++) {
                v[j] = fmaxf(acc[i][j] + bias[j], 0.f);
                acc[i][j] = 0.f;
            }
            *(float4*)&sH1[(ty * 8 + i) * 256 + tx * 8]     = make_float4(v[0], v[1], v[2], v[3]);
            *(float4*)&sH1[(ty * 8 + i) * 256 + tx * 8 + 4] = make_float4(v[4], v[5], v[6], v[7]);
        }
    }

    // ---- layer 2: h2 = relu(h1 @ W2 + b2), K=256 ----
    for (int kc = 0; kc < 256; kc += 16) {
        __syncthreads();
        {
            const float4* wv = (const float4*)(W2 + kc * 256);
            float4* sv = (float4*)sW;
#pragma unroll
            for (int i = 0; i < 4; i++) sv[tid + 256 * i] = wv[tid + 256 * i];
        }
        __syncthreads();
        mma_chunk_8x8(acc, sH1, 256, sW, tx, ty, kc);
    }

    // epilogue 2 -> sH2
    {
        float bias[8];
#pragma unroll
        for (int j = 0; j < 8; j++) bias[j] = b2[tx * 8 + j];
#pragma unroll
        for (int i = 0; i < 8; i++) {
            float v[8];
#pragma unroll
            for (int j = 0; j < 8; j++) v[j] = fmaxf(acc[i][j] + bias[j], 0.f);
            *(float4*)&sH2[(ty * 8 + i) * 256 + tx * 8]     = make_float4(v[0], v[1], v[2], v[3]);
            *(float4*)&sH2[(ty * 8 + i) * 256 + tx * 8 + 4] = make_float4(v[4], v[5], v[6], v[7]);
        }
    }

    __syncthreads();
    // ---- layer 3: g = h2 @ W3 + b3 (256 -> 5) ----
    for (int i = tid; i < 1280; i += 256) sW[i] = W3[i];
    if (tid < 5) sW[1280 + tid] = b3[tid];
    __syncthreads();

    for (int o = tid; o < 320; o += 256) {
        int row = o / 5;
        int col = o - row * 5;
        const float* h = &sH2[row * 256];
        float sum = sW[1280 + col];
#pragma unroll 8
        for (int k = 0; k < 256; k++) sum = fmaf(h[k], sW[k * 5 + col], sum);
        int grow = rowBase + row;            // = b*17 + t
        int b = grow / 17;
        int t = grow - b * 17;
        glist[((size_t)t * Bsz + b) * 5 + col] = sum;
        if (t == 0) g_lat[(size_t)b * 5 + col] = sum;
    }
}

// ---------------- Scan: 16 steps of latent dynamics ----------------
// warp-per-batch-element; weights SMEM-resident, W2 transposed with pad-33.
__global__ __launch_bounds__(256)
void scan_kernel(const float* __restrict__ ocW1, const float* __restrict__ ocb1,
                 const float* __restrict__ ocW2, const float* __restrict__ ocb2,
                 const float* __restrict__ ocW3, const float* __restrict__ ocb3,
                 const float* __restrict__ orW1, const float* __restrict__ orb1,
                 const float* __restrict__ orW2, const float* __restrict__ orb2,
                 const float* __restrict__ orW3, const float* __restrict__ orb3)
{
    __shared__ float sW2T[3][1056];        // [m][o*33 + j] = W2[m][j][o]
    __shared__ float sW1s[3][32], sB1s[3][32], sB2s[3][32];
    __shared__ float sW3s[3][64];          // [m][j*2 + c]
    __shared__ float sB3s[3][2];

    const int tid = threadIdx.x;
    const int lane = tid & 31;
    const int w = tid >> 5;

    for (int idx = tid; idx < 3072; idx += 256) {
        int m = idx >> 10, r = idx & 1023;
        int j = r >> 5, o = r & 31;
        float wv = (m < 2) ? ocW2[m * 1024 + r] : orW2[r];
        sW2T[m][o * 33 + j] = wv;
    }
    if (tid < 96) {
        int m = tid >> 5, o = tid & 31;
        sW1s[m][o] = (m < 2) ? ocW1[m * 32 + o] : orW1[o];
        sB1s[m][o] = (m < 2) ? ocb1[m * 32 + o] : orb1[o];
        sB2s[m][o] = (m < 2) ? ocb2[m * 32 + o] : orb2[o];
    }
    if (tid < 192) {
        int m = tid >> 6, r = tid & 63;
        float v;
        if (m < 2) v = ocW3[m * 64 + r];
        else { int j = r >> 1, c = r & 1; v = (c == 0) ? orW3[j] : 0.f; }
        sW3s[m][r] = v;
    }
    if (tid < 6) {
        int m = tid >> 1, c = tid & 1;
        sB3s[m][c] = (m < 2) ? ocb3[m * 2 + c] : ((c == 0) ? orb3[0] : 0.f);
    }
    __syncthreads();

    const int b = blockIdx.x * 8 + w;
    float y0 = g_lat[(size_t)b * 5 + 0];
    float y1 = g_lat[(size_t)b * 5 + 1];
    float y2 = g_lat[(size_t)b * 5 + 2];
    float y3 = g_lat[(size_t)b * 5 + 3];
    float y4 = g_lat[(size_t)b * 5 + 4];

    for (int s = 0; s < 16; s++) {
        float ins[3];
        ins[0] = fmaf(y0, y0, y1 * y1);
        ins[1] = fmaf(y2, y2, y3 * y3);
        ins[2] = y4;
        float o0[3], o1[3];
#pragma unroll
        for (int m = 0; m < 3; m++) {
            float h1 = fmaxf(fmaf(ins[m], sW1s[m][lane], sB1s[m][lane]), 0.f);
            float a = sB2s[m][lane];
            const float* w2 = &sW2T[m][lane * 33];
#pragma unroll
            for (int j = 0; j < 32; j++)
                a = fmaf(__shfl_sync(0xffffffffu, h1, j), w2[j], a);
            float h2 = fmaxf(a, 0.f);
            float p0 = h2 * sW3s[m][lane * 2 + 0];
            float p1 = h2 * sW3s[m][lane * 2 + 1];
#pragma unroll
            for (int off = 16; off; off >>= 1) {
                p0 += __shfl_xor_sync(0xffffffffu, p0, off);
                p1 += __shfl_xor_sync(0xffffffffu, p1, off);
            }
            o0[m] = p0 + sB3s[m][0];
            o1[m] = p1 + sB3s[m][1];
        }
        float sc0 = __expf(fminf(fmaxf(o1[0], -5.f), 5.f) * DTc);
        float c0 = sc0 * __cosf(o0[0] * DTc);
        float s0v = sc0 * __sinf(o0[0] * DTc);
        float sc1 = __expf(fminf(fmaxf(o1[1], -5.f), 5.f) * DTc);
        float c1 = sc1 * __cosf(o0[1] * DTc);
        float s1v = sc1 * __sinf(o0[1] * DTc);
        float rsc = __expf(fminf(fmaxf(o0[2], -5.f), 5.f) * DTc);

        float n0 = y0 * c0 - y1 * s0v;
        float n1 = y0 * s0v + y1 * c0;
        float n2 = y2 * c1 - y3 * s1v;
        float n3 = y2 * s1v + y3 * c1;
        float n4 = rsc * y4;
        y0 = n0; y1 = n1; y2 = n2; y3 = n3; y4 = n4;

        if (lane < 5) {
            float vv = (lane == 0) ? y0 : (lane == 1) ? y1 : (lane == 2) ? y2
                      : (lane == 3) ? y3 : y4;
            g_lat[((size_t)(s + 1) * Bsz + b) * 5 + lane] = vv;
        }
    }
}

// ---------------- Decoder: y_preds = MLP3(latents) ----------------
__global__ __launch_bounds__(256, 1)
void dec_kernel(const float* __restrict__ W1, const float* __restrict__ b1,
                const float* __restrict__ W2, const float* __restrict__ b2,
                const float* __restrict__ W3, const float* __restrict__ b3,
                float* __restrict__ ypred)
{
    extern __shared__ float sm[];
    float* sW  = sm;
    float* sL  = sm + 4096;
    float* sH1 = sm + 12288;
    float* sH2 = sm + 28672;

    const int tid = threadIdx.x;
    const int tx = tid & 31;
    const int ty = tid >> 5;
    const int rowBase = blockIdx.x * 64;

    // stage latent tile (64x5) and W1 (5x256)
    for (int i = tid; i < 320; i += 256) sL[i] = g_lat[(size_t)rowBase * 5 + i];
    for (int i = tid; i < 1280; i += 256) sW[i] = W1[i];
    __syncthreads();

    float acc[8][8];
#pragma unroll
    for (int i = 0; i < 8; i++)
#pragma unroll
        for (int j = 0; j < 8; j++) acc[i][j] = 0.f;

    // ---- layer 1: K=5 ----
#pragma unroll
    for (int k = 0; k < 5; k++) {
        float a[8];
#pragma unroll
        for (int i = 0; i < 8; i++) a[i] = sL[(ty * 8 + i) * 5 + k];
        const float* wr = &sW[k * 256 + tx * 8];
        float4 w0 = *(const float4*)wr;
        float4 w1 = *(const float4*)(wr + 4);
        float bb[8] = {w0.x, w0.y, w0.z, w0.w, w1.x, w1.y, w1.z, w1.w};
#pragma unroll
        for (int i = 0; i < 8; i++)
#pragma unroll
            for (int j = 0; j < 8; j++)
                acc[i][j] = fmaf(a[i], bb[j], acc[i][j]);
    }

    // epilogue 1 -> sH1
    {
        float bias[8];
#pragma unroll
        for (int j = 0; j < 8; j++) bias[j] = b1[tx * 8 + j];
#pragma unroll
        for (int i = 0; i < 8; i++) {
            float v[8];
#pragma unroll
            for (int j = 0; j < 8; j++) {
                v[j] = fmaxf(acc[i][j] + bias[j], 0.f);
                acc[i][j] = 0.f;
            }
            *(float4*)&sH1[(ty * 8 + i) * 256 + tx * 8]     = make_float4(v[0], v[1], v[2], v[3]);
            *(float4*)&sH1[(ty * 8 + i) * 256 + tx * 8 + 4] = make_float4(v[4], v[5], v[6], v[7]);
        }
    }

    // ---- layer 2: K=256 ----
    for (int kc = 0; kc < 256; kc += 16) {
        __syncthreads();
        {
            const float4* wv = (const float4*)(W2 + kc * 256);
            float4* sv = (float4*)sW;
#pragma unroll
            for (int i = 0; i < 4; i++) sv[tid + 256 * i] = wv[tid + 256 * i];
        }
        __syncthreads();
        mma_chunk_8x8(acc, sH1, 256, sW, tx, ty, kc);
    }

    // epilogue 2 -> sH2
    {
        float bias[8];
#pragma unroll
        for (int j = 0; j < 8; j++) bias[j] = b2[tx * 8 + j];
#pragma unroll
        for (int i = 0; i < 8; i++) {
            float v[8];
#pragma unroll
            for (int j = 0; j < 8; j++) v[j] = fmaxf(acc[i][j] + bias[j], 0.f);
            *(float4*)&sH2[(ty * 8 + i) * 256 + tx * 8]     = make_float4(v[0], v[1], v[2], v[3]);
            *(float4*)&sH2[(ty * 8 + i) * 256 + tx * 8 + 4] = make_float4(v[4], v[5], v[6], v[7]);
        }
    }

    // ---- layer 3: out = h2 @ W3 + b3 (256 -> 128), 8x4 tiles ----
    float acc3[8][4];
#pragma unroll
    for (int i = 0; i < 8; i++)
#pragma unroll
        for (int j = 0; j < 4; j++) acc3[i][j] = 0.f;

    for (int kc = 0; kc < 256; kc += 16) {
        __syncthreads();
        {
            const float4* wv = (const float4*)(W3 + kc * 128);
            float4* sv = (float4*)sW;
#pragma unroll
            for (int i = 0; i < 2; i++) sv[tid + 256 * i] = wv[tid + 256 * i];
        }
        __syncthreads();
#pragma unroll
        for (int kk = 0; kk < 16; kk += 4) {
            float4 a4[8];
#pragma unroll
            for (int i = 0; i < 8; i++)
                a4[i] = *(const float4*)&sH2[(ty * 8 + i) * 256 + kc + kk];
#pragma unroll
            for (int u = 0; u < 4; u++) {
                float4 wv = *(const float4*)&sW[(kk + u) * 128 + tx * 4];
                float bb[4] = {wv.x, wv.y, wv.z, wv.w};
#pragma unroll
                for (int i = 0; i < 8; i++) {
                    float av = (u == 0) ? a4[i].x : (u == 1) ? a4[i].y
                              : (u == 2) ? a4[i].z : a4[i].w;
#pragma unroll
                    for (int j = 0; j < 4; j++)
                        acc3[i][j] = fmaf(av, bb[j], acc3[i][j]);
                }
            }
        }
    }

    // epilogue 3 -> global
    {
        float bias[4];
#pragma unroll
        for (int j = 0; j < 4; j++) bias[j] = b3[tx * 4 + j];
#pragma unroll
        for (int i = 0; i < 8; i++) {
            float4 v = make_float4(acc3[i][0] + bias[0], acc3[i][1] + bias[1],
                                   acc3[i][2] + bias[2], acc3[i][3] + bias[3]);
            *(float4*)&ypred[(size_t)(rowBase + ty * 8 + i) * 128 + tx * 4] = v;
        }
    }
}

extern "C" void kernel_launch(void* const* d_in, const int* in_sizes, int n_in,
                              void* d_out, int out_size)
{
    const float* x    = (const float*)d_in[0];
    const float* eW1  = (const float*)d_in[1];
    const float* eb1  = (const float*)d_in[2];
    const float* eW2  = (const float*)d_in[3];
    const float* eb2  = (const float*)d_in[4];
    const float* eW3  = (const float*)d_in[5];
    const float* eb3  = (const float*)d_in[6];
    const float* dW1  = (const float*)d_in[7];
    const float* db1  = (const float*)d_in[8];
    const float* dW2  = (const float*)d_in[9];
    const float* db2  = (const float*)d_in[10];
    const float* dW3  = (const float*)d_in[11];
    const float* db3  = (const float*)d_in[12];
    const float* ocW1 = (const float*)d_in[13];
    const float* ocb1 = (const float*)d_in[14];
    const float* ocW2 = (const float*)d_in[15];
    const float* ocb2 = (const float*)d_in[16];
    const float* ocW3 = (const float*)d_in[17];
    const float* ocb3 = (const float*)d_in[18];
    const float* orW1 = (const float*)d_in[19];
    const float* orb1 = (const float*)d_in[20];
    const float* orW2 = (const float*)d_in[21];
    const float* orb2 = (const float*)d_in[22];
    const float* orW3 = (const float*)d_in[23];
    const float* orb3 = (const float*)d_in[24];

    float* out   = (float*)d_out;
    float* ypred = out;                                   // (17, B, 128)
    float* glist = out + (size_t)Tn * Bsz * Nn;           // (17, B, 5)

    cudaFuncSetAttribute(enc_kernel, cudaFuncAttributeMaxDynamicSharedMemorySize, ARENA_BYTES);
    cudaFuncSetAttribute(dec_kernel, cudaFuncAttributeMaxDynamicSharedMemorySize, ARENA_BYTES);

    enc_kernel<<<(Bsz * Tn) / 64, 256, ARENA_BYTES>>>(x, eW1, eb1, eW2, eb2, eW3, eb3, glist);
    scan_kernel<<<Bsz / 8, 256>>>(ocW1, ocb1, ocW2, ocb2, ocW3, ocb3,
                                  orW1, orb1, orW2, orb2, orW3, orb3);
    dec_kernel<<<(Bsz * Tn) / 64, 256, ARENA_BYTES>>>(dW1, db1, dW2, db2, dW3, db3, ypred);
}

// round 2
// speedup vs baseline: 2.5826x; 2.5826x over previous
#include <cuda_runtime.h>
#include <cstdint>

// Problem constants
#define Bsz 16384
#define Tn  17
#define Nn  128
#define Hn  256
#define Dn  5
#define Sn  16
#define DTc 0.01f

#define MROWS_TOTAL (Bsz * Tn)      // 278528
#define BLK_M 128
#define NBLOCKS (MROWS_TOTAL / BLK_M)  // 2176

// Latents scratch: (S+1, B, D) fp32
__device__ float g_lat[(Sn + 1) * Bsz * Dn];

// ---------------- shared-memory arena (floats) ----------------
//  sA : 128 x 260  (A/H tiles; layer1 enc uses stride 132 inside same region)
//  sB : 32  x 264  (weight chunk, padded)
//  sS : small (biases, tiny weights, latents)
#define SA_OFF 0
#define SA_FLOATS (128 * 260)        // 33280
#define SB_OFF SA_FLOATS
#define SB_FLOATS (32 * 264)         // 8448
#define SS_OFF (SA_FLOATS + SB_FLOATS)
#define SS_FLOATS 2816
#define ARENA_FLOATS (SA_FLOATS + SB_FLOATS + SS_FLOATS)   // 44544
#define ARENA_BYTES  (ARENA_FLOATS * 4)                    // 178176

// tf32 round-to-nearest helpers
__device__ __forceinline__ float tf32r(float f) {
    uint32_t u;
    asm("cvt.rna.tf32.f32 %0, %1;" : "=r"(u) : "f"(f));
    return __uint_as_float(u);
}
__device__ __forceinline__ float4 tf32r4(float4 v) {
    return make_float4(tf32r(v.x), tf32r(v.y), tf32r(v.z), tf32r(v.w));
}

__device__ __forceinline__ void mma8(float c[4],
    uint32_t a0, uint32_t a1, uint32_t a2, uint32_t a3,
    uint32_t b0, uint32_t b1)
{
    asm volatile(
        "mma.sync.aligned.m16n8k8.row.col.f32.tf32.tf32.f32 "
        "{%0,%1,%2,%3}, {%4,%5,%6,%7}, {%8,%9}, {%0,%1,%2,%3};\n"
        : "+f"(c[0]), "+f"(c[1]), "+f"(c[2]), "+f"(c[3])
        : "r"(a0), "r"(a1), "r"(a2), "r"(a3), "r"(b0), "r"(b1));
}

// one staged K-chunk of 32 (4 x k8 steps); warp tile 16 x (NT*8)
template <int NT, int AS, int BS, int WNW>
__device__ __forceinline__ void mma_chunk(float c[][4],
    const float* __restrict__ sA, const float* __restrict__ sB,
    int wm, int wn, int g, int tig, int kcA)
{
#pragma unroll
    for (int kk8 = 0; kk8 < 32; kk8 += 8) {
        const float* aR = sA + (wm * 16 + g) * AS + kcA + kk8 + tig;
        uint32_t a0 = __float_as_uint(aR[0]);
        uint32_t a1 = __float_as_uint(aR[8 * AS]);
        uint32_t a2 = __float_as_uint(aR[4]);
        uint32_t a3 = __float_as_uint(aR[8 * AS + 4]);
        const float* bR = sB + (kk8 + tig) * BS + wn * WNW + g;
#pragma unroll
        for (int nt = 0; nt < NT; nt++) {
            uint32_t b0 = __float_as_uint(bR[nt * 8]);
            uint32_t b1 = __float_as_uint(bR[nt * 8 + 4 * BS]);
            mma8(c[nt], a0, a1, a2, a3, b0, b1);
        }
    }
}

// prefetch next 32xN weight chunk into regs (N=256 -> 4 f4/thread)
__device__ __forceinline__ void ldW256(float4 wbuf[4], const float* __restrict__ W,
                                       int kc, int tid)
{
#pragma unroll
    for (int j = 0; j < 4; j++) {
        int idx4 = tid + j * 512;
        int kr = idx4 >> 6, n4 = idx4 & 63;
        wbuf[j] = __ldg((const float4*)(W + (size_t)(kc + kr) * 256 + n4 * 4));
    }
}
__device__ __forceinline__ void stW256(const float4 wbuf[4], float* sB, int tid)
{
#pragma unroll
    for (int j = 0; j < 4; j++) {
        int idx4 = tid + j * 512;
        int kr = idx4 >> 6, n4 = idx4 & 63;
        *(float4*)&sB[kr * 264 + n4 * 4] = tf32r4(wbuf[j]);
    }
}

// ================= Encoder =================
__global__ __launch_bounds__(512, 1)
void enc_kernel(const float* __restrict__ x,
                const float* __restrict__ W1, const float* __restrict__ b1,
                const float* __restrict__ W2, const float* __restrict__ b2,
                const float* __restrict__ W3, const float* __restrict__ b3,
                float* __restrict__ glist)
{
    extern __shared__ float sm[];
    float* sA = sm + SA_OFF;
    float* sB = sm + SB_OFF;
    float* sS = sm + SS_OFF;   // b1@0(256) b2@256(256) W3@512(1280) b3@1792(5)

    const int tid = threadIdx.x;
    const int lane = tid & 31;
    const int g = lane >> 2, tig = lane & 3;
    const int wid = tid >> 5;
    const int wm = wid >> 1, wn = wid & 1;
    const int rowBase = blockIdx.x * BLK_M;

    // stage small weights
    if (tid < 256) { sS[tid] = b1[tid]; sS[256 + tid] = b2[tid]; }
    for (int i = tid; i < 1280; i += 512) sS[512 + i] = W3[i];
    if (tid < 5) sS[1792 + tid] = b3[tid];

    // stage X tile (128x128, tf32, stride 132)
    {
        const float4* xv = (const float4*)(x + (size_t)rowBase * Nn);
#pragma unroll
        for (int j = 0; j < 8; j++) {
            int idx4 = tid + j * 512;
            int r = idx4 >> 5, c4 = idx4 & 31;
            *(float4*)&sA[r * 132 + c4 * 4] = tf32r4(xv[r * 32 + c4]);
        }
    }

    float4 wbuf[4];
    ldW256(wbuf, W1, 0, tid);

    float c[16][4];
#pragma unroll
    for (int i = 0; i < 16; i++)
#pragma unroll
        for (int j = 0; j < 4; j++) c[i][j] = 0.f;

    // ---- layer 1: K=128 ----
    for (int kc = 0; kc < 128; kc += 32) {
        __syncthreads();
        stW256(wbuf, sB, tid);
        __syncthreads();
        if (kc < 96) ldW256(wbuf, W1, kc + 32, tid);
        mma_chunk<16, 132, 264, 128>(c, sA, sB, wm, wn, g, tig, kc);
    }
    ldW256(wbuf, W2, 0, tid);
    __syncthreads();

    // epilogue 1 -> sA (stride 260, tf32)
    {
        int r0 = wm * 16 + g, r1 = r0 + 8;
#pragma unroll
        for (int nt = 0; nt < 16; nt++) {
            int col0 = wn * 128 + nt * 8 + tig * 2;
            float bv0 = sS[col0], bv1 = sS[col0 + 1];
            float h00 = fmaxf(c[nt][0] + bv0, 0.f);
            float h01 = fmaxf(c[nt][1] + bv1, 0.f);
            float h10 = fmaxf(c[nt][2] + bv0, 0.f);
            float h11 = fmaxf(c[nt][3] + bv1, 0.f);
            *(float2*)&sA[r0 * 260 + col0] = make_float2(tf32r(h00), tf32r(h01));
            *(float2*)&sA[r1 * 260 + col0] = make_float2(tf32r(h10), tf32r(h11));
            c[nt][0] = c[nt][1] = c[nt][2] = c[nt][3] = 0.f;
        }
    }

    // ---- layer 2: K=256 ----
    for (int kc = 0; kc < 256; kc += 32) {
        __syncthreads();
        stW256(wbuf, sB, tid);
        __syncthreads();
        if (kc < 224) ldW256(wbuf, W2, kc + 32, tid);
        mma_chunk<16, 260, 264, 128>(c, sA, sB, wm, wn, g, tig, kc);
    }
    __syncthreads();

    // epilogue 2 -> sA (h2, tf32-rounded fp32 values; scalar layer3 reads them)
    {
        int r0 = wm * 16 + g, r1 = r0 + 8;
#pragma unroll
        for (int nt = 0; nt < 16; nt++) {
            int col0 = wn * 128 + nt * 8 + tig * 2;
            float bv0 = sS[256 + col0], bv1 = sS[256 + col0 + 1];
            float h00 = fmaxf(c[nt][0] + bv0, 0.f);
            float h01 = fmaxf(c[nt][1] + bv1, 0.f);
            float h10 = fmaxf(c[nt][2] + bv0, 0.f);
            float h11 = fmaxf(c[nt][3] + bv1, 0.f);
            *(float2*)&sA[r0 * 260 + col0] = make_float2(h00, h01);
            *(float2*)&sA[r1 * 260 + col0] = make_float2(h10, h11);
        }
    }
    __syncthreads();

    // ---- layer 3: 256 -> 5 (scalar fp32) ----
    for (int o = tid; o < BLK_M * 5; o += 512) {
        int row = o / 5;
        int col = o - row * 5;
        const float* h = sA + row * 260;
        const float* w = sS + 512 + col;
        float sum = sS[1792 + col];
#pragma unroll 8
        for (int k = 0; k < 256; k++) sum = fmaf(h[k], w[k * 5], sum);
        int grow = rowBase + row;
        int b = grow / 17;
        int t = grow - b * 17;
        glist[((size_t)t * Bsz + b) * 5 + col] = sum;
        if (t == 0) g_lat[(size_t)b * 5 + col] = sum;
    }
}

// ================= Scan (unchanged from R1) =================
__global__ __launch_bounds__(256)
void scan_kernel(const float* __restrict__ ocW1, const float* __restrict__ ocb1,
                 const float* __restrict__ ocW2, const float* __restrict__ ocb2,
                 const float* __restrict__ ocW3, const float* __restrict__ ocb3,
                 const float* __restrict__ orW1, const float* __restrict__ orb1,
                 const float* __restrict__ orW2, const float* __restrict__ orb2,
                 const float* __restrict__ orW3, const float* __restrict__ orb3)
{
    __shared__ float sW2T[3][1056];
    __shared__ float sW1s[3][32], sB1s[3][32], sB2s[3][32];
    __shared__ float sW3s[3][64];
    __shared__ float sB3s[3][2];

    const int tid = threadIdx.x;
    const int lane = tid & 31;
    const int w = tid >> 5;

    for (int idx = tid; idx < 3072; idx += 256) {
        int m = idx >> 10, r = idx & 1023;
        int j = r >> 5, o = r & 31;
        float wv = (m < 2) ? ocW2[m * 1024 + r] : orW2[r];
        sW2T[m][o * 33 + j] = wv;
    }
    if (tid < 96) {
        int m = tid >> 5, o = tid & 31;
        sW1s[m][o] = (m < 2) ? ocW1[m * 32 + o] : orW1[o];
        sB1s[m][o] = (m < 2) ? ocb1[m * 32 + o] : orb1[o];
        sB2s[m][o] = (m < 2) ? ocb2[m * 32 + o] : orb2[o];
    }
    if (tid < 192) {
        int m = tid >> 6, r = tid & 63;
        float v;
        if (m < 2) v = ocW3[m * 64 + r];
        else { int j = r >> 1, cc = r & 1; v = (cc == 0) ? orW3[j] : 0.f; }
        sW3s[m][r] = v;
    }
    if (tid < 6) {
        int m = tid >> 1, cc = tid & 1;
        sB3s[m][cc] = (m < 2) ? ocb3[m * 2 + cc] : ((cc == 0) ? orb3[0] : 0.f);
    }
    __syncthreads();

    const int b = blockIdx.x * 8 + w;
    float y0 = g_lat[(size_t)b * 5 + 0];
    float y1 = g_lat[(size_t)b * 5 + 1];
    float y2 = g_lat[(size_t)b * 5 + 2];
    float y3 = g_lat[(size_t)b * 5 + 3];
    float y4 = g_lat[(size_t)b * 5 + 4];

    for (int s = 0; s < 16; s++) {
        float ins[3];
        ins[0] = fmaf(y0, y0, y1 * y1);
        ins[1] = fmaf(y2, y2, y3 * y3);
        ins[2] = y4;
        float o0[3], o1[3];
#pragma unroll
        for (int m = 0; m < 3; m++) {
            float h1 = fmaxf(fmaf(ins[m], sW1s[m][lane], sB1s[m][lane]), 0.f);
            float a = sB2s[m][lane];
            const float* w2 = &sW2T[m][lane * 33];
#pragma unroll
            for (int j = 0; j < 32; j++)
                a = fmaf(__shfl_sync(0xffffffffu, h1, j), w2[j], a);
            float h2 = fmaxf(a, 0.f);
            float p0 = h2 * sW3s[m][lane * 2 + 0];
            float p1 = h2 * sW3s[m][lane * 2 + 1];
#pragma unroll
            for (int off = 16; off; off >>= 1) {
                p0 += __shfl_xor_sync(0xffffffffu, p0, off);
                p1 += __shfl_xor_sync(0xffffffffu, p1, off);
            }
            o0[m] = p0 + sB3s[m][0];
            o1[m] = p1 + sB3s[m][1];
        }
        float sc0 = __expf(fminf(fmaxf(o1[0], -5.f), 5.f) * DTc);
        float c0 = sc0 * __cosf(o0[0] * DTc);
        float s0v = sc0 * __sinf(o0[0] * DTc);
        float sc1 = __expf(fminf(fmaxf(o1[1], -5.f), 5.f) * DTc);
        float c1 = sc1 * __cosf(o0[1] * DTc);
        float s1v = sc1 * __sinf(o0[1] * DTc);
        float rsc = __expf(fminf(fmaxf(o0[2], -5.f), 5.f) * DTc);

        float n0 = y0 * c0 - y1 * s0v;
        float n1 = y0 * s0v + y1 * c0;
        float n2 = y2 * c1 - y3 * s1v;
        float n3 = y2 * s1v + y3 * c1;
        float n4 = rsc * y4;
        y0 = n0; y1 = n1; y2 = n2; y3 = n3; y4 = n4;

        if (lane < 5) {
            float vv = (lane == 0) ? y0 : (lane == 1) ? y1 : (lane == 2) ? y2
                      : (lane == 3) ? y3 : y4;
            g_lat[((size_t)(s + 1) * Bsz + b) * 5 + lane] = vv;
        }
    }
}

// ================= Decoder =================
__global__ __launch_bounds__(512, 1)
void dec_kernel(const float* __restrict__ W1, const float* __restrict__ b1,
                const float* __restrict__ W2, const float* __restrict__ b2,
                const float* __restrict__ W3, const float* __restrict__ b3,
                float* __restrict__ ypred)
{
    extern __shared__ float sm[];
    float* sA = sm + SA_OFF;
    float* sB = sm + SB_OFF;
    float* sS = sm + SS_OFF;  // b1@0(256) b2@256(256) W1@512(1280) b3@1792(128) lat@2048(640)

    const int tid = threadIdx.x;
    const int lane = tid & 31;
    const int g = lane >> 2, tig = lane & 3;
    const int wid = tid >> 5;
    const int wm = wid >> 1, wn = wid & 1;
    const int rowBase = blockIdx.x * BLK_M;

    if (tid < 256) { sS[tid] = b1[tid]; sS[256 + tid] = b2[tid]; }
    for (int i = tid; i < 1280; i += 512) sS[512 + i] = W1[i];
    if (tid < 128) sS[1792 + tid] = b3[tid];
    for (int i = tid; i < BLK_M * 5; i += 512) sS[2048 + i] = g_lat[(size_t)rowBase * 5 + i];

    float4 wbuf[4];
    ldW256(wbuf, W2, 0, tid);
    __syncthreads();

    // ---- layer 1: 5 -> 256 scalar, tf32 into sA (stride 260) ----
    for (int o = tid; o < BLK_M * 256; o += 512) {
        int row = o >> 8, col = o & 255;
        const float* l = sS + 2048 + row * 5;
        const float* w = sS + 512 + col;
        float s = sS[col];
        s = fmaf(l[0], w[0],    s);
        s = fmaf(l[1], w[256],  s);
        s = fmaf(l[2], w[512],  s);
        s = fmaf(l[3], w[768],  s);
        s = fmaf(l[4], w[1024], s);
        sA[row * 260 + col] = tf32r(fmaxf(s, 0.f));
    }

    float c[16][4];
#pragma unroll
    for (int i = 0; i < 16; i++)
#pragma unroll
        for (int j = 0; j < 4; j++) c[i][j] = 0.f;

    // ---- layer 2: K=256, N=256 ----
    for (int kc = 0; kc < 256; kc += 32) {
        __syncthreads();
        stW256(wbuf, sB, tid);
        __syncthreads();
        if (kc < 224) ldW256(wbuf, W2, kc + 32, tid);
        mma_chunk<16, 260, 264, 128>(c, sA, sB, wm, wn, g, tig, kc);
    }
    __syncthreads();

    // epilogue 2 -> sA (tf32)
    {
        int r0 = wm * 16 + g, r1 = r0 + 8;
#pragma unroll
        for (int nt = 0; nt < 16; nt++) {
            int col0 = wn * 128 + nt * 8 + tig * 2;
            float bv0 = sS[256 + col0], bv1 = sS[256 + col0 + 1];
            float h00 = fmaxf(c[nt][0] + bv0, 0.f);
            float h01 = fmaxf(c[nt][1] + bv1, 0.f);
            float h10 = fmaxf(c[nt][2] + bv0, 0.f);
            float h11 = fmaxf(c[nt][3] + bv1, 0.f);
            *(float2*)&sA[r0 * 260 + col0] = make_float2(tf32r(h00), tf32r(h01));
            *(float2*)&sA[r1 * 260 + col0] = make_float2(tf32r(h10), tf32r(h11));
            c[nt][0] = c[nt][1] = c[nt][2] = c[nt][3] = 0.f;
        }
    }

    // ---- layer 3: K=256, N=128 (stride 136 B tile) ----
    float4 w3buf[2];
#pragma unroll
    for (int j = 0; j < 2; j++) {
        int idx4 = tid + j * 512;
        int kr = idx4 >> 5, n4 = idx4 & 31;
        w3buf[j] = __ldg((const float4*)(W3 + (size_t)kr * 128 + n4 * 4));
    }

    for (int kc = 0; kc < 256; kc += 32) {
        __syncthreads();
#pragma unroll
        for (int j = 0; j < 2; j++) {
            int idx4 = tid + j * 512;
            int kr = idx4 >> 5, n4 = idx4 & 31;
            *(float4*)&sB[kr * 136 + n4 * 4] = tf32r4(w3buf[j]);
        }
        __syncthreads();
        if (kc < 224) {
#pragma unroll
            for (int j = 0; j < 2; j++) {
                int idx4 = tid + j * 512;
                int kr = idx4 >> 5, n4 = idx4 & 31;
                w3buf[j] = __ldg((const float4*)(W3 + (size_t)(kc + 32 + kr) * 128 + n4 * 4));
            }
        }
        mma_chunk<8, 260, 136, 64>(c, sA, sB, wm, wn, g, tig, kc);
    }

    // epilogue 3 -> global (fp32)
    {
        int r0 = rowBase + wm * 16 + g;
        int r1 = r0 + 8;
#pragma unroll
        for (int nt = 0; nt < 8; nt++) {
            int col0 = wn * 64 + nt * 8 + tig * 2;
            float bv0 = sS[1792 + col0], bv1 = sS[1792 + col0 + 1];
            *(float2*)&ypred[(size_t)r0 * 128 + col0] =
                make_float2(c[nt][0] + bv0, c[nt][1] + bv1);
            *(float2*)&ypred[(size_t)r1 * 128 + col0] =
                make_float2(c[nt][2] + bv0, c[nt][3] + bv1);
        }
    }
}

extern "C" void kernel_launch(void* const* d_in, const int* in_sizes, int n_in,
                              void* d_out, int out_size)
{
    const float* x    = (const float*)d_in[0];
    const float* eW1  = (const float*)d_in[1];
    const float* eb1  = (const float*)d_in[2];
    const float* eW2  = (const float*)d_in[3];
    const float* eb2  = (const float*)d_in[4];
    const float* eW3  = (const float*)d_in[5];
    const float* eb3  = (const float*)d_in[6];
    const float* dW1  = (const float*)d_in[7];
    const float* db1  = (const float*)d_in[8];
    const float* dW2  = (const float*)d_in[9];
    const float* db2  = (const float*)d_in[10];
    const float* dW3  = (const float*)d_in[11];
    const float* db3  = (const float*)d_in[12];
    const float* ocW1 = (const float*)d_in[13];
    const float* ocb1 = (const float*)d_in[14];
    const float* ocW2 = (const float*)d_in[15];
    const float* ocb2 = (const float*)d_in[16];
    const float* ocW3 = (const float*)d_in[17];
    const float* ocb3 = (const float*)d_in[18];
    const float* orW1 = (const float*)d_in[19];
    const float* orb1 = (const float*)d_in[20];
    const float* orW2 = (const float*)d_in[21];
    const float* orb2 = (const float*)d_in[22];
    const float* orW3 = (const float*)d_in[23];
    const float* orb3 = (const float*)d_in[24];

    float* out   = (float*)d_out;
    float* ypred = out;                                   // (17, B, 128)
    float* glist = out + (size_t)Tn * Bsz * Nn;           // (17, B, 5)

    cudaFuncSetAttribute(enc_kernel, cudaFuncAttributeMaxDynamicSharedMemorySize, ARENA_BYTES);
    cudaFuncSetAttribute(dec_kernel, cudaFuncAttributeMaxDynamicSharedMemorySize, ARENA_BYTES);

    enc_kernel<<<NBLOCKS, 512, ARENA_BYTES>>>(x, eW1, eb1, eW2, eb2, eW3, eb3, glist);
    scan_kernel<<<Bsz / 8, 256>>>(ocW1, ocb1, ocW2, ocb2, ocW3, ocb3,
                                  orW1, orb1, orW2, orb2, orW3, orb3);
    dec_kernel<<<NBLOCKS, 512, ARENA_BYTES>>>(dW1, db1, dW2, db2, dW3, db3, ypred);
}